// round 6
// baseline (speedup 1.0000x reference)
#include <cuda_runtime.h>
#include <cuda_fp16.h>

#define D 64
#define MAXN 20000
#define MAXE 320000
#define STEP 0.01f
#define NLAYERS 10
#define SCB 256
#define PADH 72   // padded row stride in halves (144 B) -> conflict-free LDS.128

// ---------------- device scratch ----------------
__device__ __half g_Ah[(size_t)MAXN * D * D];   // fp16 copy of A (164 MB)
__device__ float g_tsys[2][MAXN * 128];         // per-node [ts(64)|ys(64)], double buffered
__device__ float g_vs[2][MAXN];
__device__ float g_gprev[MAXN * D];
__device__ float g_invdeg[MAXN];
__device__ int   g_cnts[MAXN];                  // zero at load; re-zeroed by cleanup
__device__ int   g_cntd[MAXN];
__device__ int   g_partial[128];
__device__ int   g_rowstart[MAXN + 1];
__device__ int   g_cursor[MAXN];
__device__ int   g_srcidx[MAXE];

// ---------------- cp.async helpers ----------------
__device__ __forceinline__ void cp_async16(void* smem, const void* gmem) {
    unsigned s = (unsigned)__cvta_generic_to_shared(smem);
    asm volatile("cp.async.cg.shared.global [%0], [%1], 16;\n" :: "r"(s), "l"(gmem));
}
__device__ __forceinline__ void cp_commit() { asm volatile("cp.async.commit_group;\n"); }
__device__ __forceinline__ void cp_wait0()  { asm volatile("cp.async.wait_group 0;\n"); }

// ---------------- A fp32 -> fp16 (one pass) ----------------
// each thread: 8 floats -> 8 halves (16B store)
__global__ void k_convert(const float* __restrict__ A, int total8) {
    int i = blockIdx.x * blockDim.x + threadIdx.x;
    if (i >= total8) return;
    const float4* src = (const float4*)A + 2 * (size_t)i;
    float4 f0 = __ldcs(src);
    float4 f1 = __ldcs(src + 1);
    __half2 h[4];
    h[0] = __floats2half2_rn(f0.x, f0.y);
    h[1] = __floats2half2_rn(f0.z, f0.w);
    h[2] = __floats2half2_rn(f1.x, f1.y);
    h[3] = __floats2half2_rn(f1.z, f1.w);
    ((uint4*)g_Ah)[i] = *(const uint4*)h;
}

// ---------------- setup ----------------
__global__ void k_count(const int* __restrict__ src,
                        const int* __restrict__ dst, int E) {
    int e = blockIdx.x * blockDim.x + threadIdx.x;
    if (e < E) {
        atomicAdd(&g_cnts[src[e]], 1);
        atomicAdd(&g_cntd[dst[e]], 1);
    }
}

__global__ void k_prep_deg(int N) {
    __shared__ int s[SCB];
    int i = blockIdx.x * SCB + threadIdx.x;
    int c = 0;
    if (i < N) {
        g_invdeg[i] = 1.0f / (1.0f + (float)g_cnts[i]);
        c = g_cntd[i];
    }
    s[threadIdx.x] = c;
    __syncthreads();
    for (int o = SCB / 2; o > 0; o >>= 1) {
        if (threadIdx.x < o) s[threadIdx.x] += s[threadIdx.x + o];
        __syncthreads();
    }
    if (threadIdx.x == 0) g_partial[blockIdx.x] = s[0];
}

__global__ void k_scan_partials(int nb, int N, int E) {
    __shared__ int s[128];
    int t = threadIdx.x;
    int v = (t < nb) ? g_partial[t] : 0;
    s[t] = v;
    __syncthreads();
    for (int o = 1; o < 128; o <<= 1) {
        int a = (t >= o) ? s[t - o] : 0;
        __syncthreads();
        s[t] += a;
        __syncthreads();
    }
    if (t < nb) g_partial[t] = s[t] - v;   // exclusive
    if (t == 0) g_rowstart[N] = E;
}

__global__ void k_rowfill(int N) {
    __shared__ int s[SCB];
    int i = blockIdx.x * SCB + threadIdx.x;
    int c = (i < N) ? g_cntd[i] : 0;
    s[threadIdx.x] = c;
    __syncthreads();
    for (int o = 1; o < SCB; o <<= 1) {
        int a = (threadIdx.x >= o) ? s[threadIdx.x - o] : 0;
        __syncthreads();
        s[threadIdx.x] += a;
        __syncthreads();
    }
    if (i < N) {
        int excl = s[threadIdx.x] - c + g_partial[blockIdx.x];
        g_rowstart[i] = excl;
        g_cursor[i]   = excl;
    }
}

__global__ void k_fill(const int* __restrict__ src,
                       const int* __restrict__ dst, int E) {
    int e = blockIdx.x * blockDim.x + threadIdx.x;
    if (e < E) {
        int pos = atomicAdd(&g_cursor[dst[e]], 1);
        g_srcidx[pos] = src[e];
    }
}

// ---------------- stage a 64x64 fp16 tile pair via cp.async ----------------
__device__ __forceinline__ void stage_tiles(__half (*tile)[D * PADH],
                                            int blk, int tid, int N) {
#pragma unroll
    for (int nd = 0; nd < 2; nd++) {
        int nn = min(blk * 2 + nd, N - 1);
        const __half* src = g_Ah + (size_t)nn * (D * D);
#pragma unroll
        for (int k = 0; k < 4; k++) {
            int q = k * 128 + tid;          // 16B chunk id, 0..511 (8 halves each)
            int r = q >> 3;
            int c = (q & 7) * 8;
            cp_async16(&tile[nd][r * PADH + c], src + q * 8);
        }
    }
    cp_commit();
}

// GEMV row dot from fp16 smem tile, fp32 x in smem, fp32 accumulate
__device__ __forceinline__ float gemv_row(const __half* row, const float* xv) {
    float acc = 0.0f;
#pragma unroll
    for (int j = 0; j < 8; j++) {
        uint4 pk = *(const uint4*)(row + 8 * j);
        const __half2* hp = (const __half2*)&pk;
        float4 x0 = *(const float4*)(xv + 8 * j);
        float4 x1 = *(const float4*)(xv + 8 * j + 4);
        float2 f0 = __half22float2(hp[0]);
        float2 f1 = __half22float2(hp[1]);
        float2 f2 = __half22float2(hp[2]);
        float2 f3 = __half22float2(hp[3]);
        acc += f0.x * x0.x + f0.y * x0.y + f1.x * x0.z + f1.y * x0.w;
        acc += f2.x * x1.x + f2.y * x1.y + f3.x * x1.z + f3.y * x1.w;
    }
    return acc;
}

// ---------------- grad_init: 2 nodes / 128 threads ----------------
__global__ void __launch_bounds__(128) k_grad_init(
        const float* __restrict__ b, const float* __restrict__ x, int N) {
    __shared__ __align__(16) __half tile[2][D * PADH];
    __shared__ __align__(16) float xs[2][D];
    int tid = threadIdx.x;
    int local = tid >> 6;
    int t = tid & 63;
    int n = blockIdx.x * 2 + local;
    bool ok = (n < N);
    int nc = ok ? n : (N - 1);

    stage_tiles(tile, blockIdx.x, tid, N);
    xs[local][t] = x[nc * D + t];
    cp_wait0();
    __syncthreads();

    float acc = gemv_row(&tile[local][t * PADH], xs[local]);
    if (!ok) return;
    float g = 2.0f * acc + b[n * D + t];
    float id = g_invdeg[n];
    g_gprev[n * D + t] = g;
    g_tsys[0][n * 128 + t]      = (xs[local][t] - STEP * g) * id;
    g_tsys[0][n * 128 + 64 + t] = g * id;
    if (t == 0) g_vs[0][n] = id;
}

// ---------------- fused per-layer kernel: 2 nodes / 128 threads ----------------
__global__ void __launch_bounds__(128) k_layer(
        const float* __restrict__ b, float* __restrict__ out,
        int ib, int ob, int last, int N) {
    __shared__ __align__(16) __half tile[2][D * PADH];
    __shared__ __align__(16) float sh[2][128];
    __shared__ float shv[2];
    int tid = threadIdx.x;
    int local = tid >> 6;
    int t = tid & 63;
    int n = blockIdx.x * 2 + local;
    bool ok = (n < N);
    int nc = ok ? n : (N - 1);

    // 1) A stream starts immediately
    stage_tiles(tile, blockIdx.x, tid, N);

    // 2) gather (mix): 4-way unrolled independent loads (MLP=4/thread)
    // float2 slot t covers floats (2t,2t+1) of the node's [ts|ys] record
    const float2* tin = (const float2*)g_tsys[ib];
    const float* vin = g_vs[ib];
    int rs = g_rowstart[nc];
    int re = g_rowstart[nc + 1];
    float2 a0 = tin[nc * 64 + t];       // self term (pre-scaled)
    float2 a1 = {0.f, 0.f}, a2 = {0.f, 0.f}, a3 = {0.f, 0.f};
    float vacc = (t == 0) ? vin[nc] : 0.0f;

    int k = rs;
    for (; k + 4 <= re; k += 4) {
        int s0 = g_srcidx[k];
        int s1 = g_srcidx[k + 1];
        int s2 = g_srcidx[k + 2];
        int s3 = g_srcidx[k + 3];
        float2 v0 = tin[s0 * 64 + t];
        float2 v1 = tin[s1 * 64 + t];
        float2 v2 = tin[s2 * 64 + t];
        float2 v3 = tin[s3 * 64 + t];
        a0.x += v0.x; a0.y += v0.y;
        a1.x += v1.x; a1.y += v1.y;
        a2.x += v2.x; a2.y += v2.y;
        a3.x += v3.x; a3.y += v3.y;
        if (t == 0) vacc += vin[s0] + vin[s1] + vin[s2] + vin[s3];
    }
    for (; k < re; k++) {
        int s = g_srcidx[k];
        float2 v = tin[s * 64 + t];
        a0.x += v.x; a0.y += v.y;
        if (t == 0) vacc += vin[s];
    }
    float2 acc;
    acc.x = (a0.x + a1.x) + (a2.x + a3.x);
    acc.y = (a0.y + a1.y) + (a2.y + a3.y);

    // reconstruct mixed record: sh[0..63]=u_new, sh[64..127]=ny
    sh[local][2 * t]     = acc.x;
    sh[local][2 * t + 1] = acc.y;
    if (t == 0) shv[local] = vacc;
    __syncthreads();

    float u_r  = sh[local][t];
    float ny_r = sh[local][64 + t];
    float vnew = shv[local];
    float x1 = u_r / vnew;
    sh[local][t] = x1;            // own-slot overwrite (x vector for GEMV)
    cp_wait0();
    __syncthreads();

    // 3) GEMV from fp16 smem tile
    float accg = gemv_row(&tile[local][t * PADH], sh[local]);
    if (!ok) return;

    float g1 = 2.0f * accg + b[n * D + t];
    float ynew = ny_r + g1 - g_gprev[n * D + t];
    g_gprev[n * D + t] = g1;

    if (last) {
        out[n * D + t] = x1;
    } else {
        float id = g_invdeg[n];
        g_tsys[ob][n * 128 + t]      = (u_r - STEP * ynew) * id;
        g_tsys[ob][n * 128 + 64 + t] = ynew * id;
        if (t == 0) g_vs[ob][n] = vnew * id;
    }
}

// cleanup: re-zero counters for next graph replay + emit comm_cost tail
__global__ void k_cleanup(float* out, int base, int extra, long long comm, int N) {
    int i = blockIdx.x * blockDim.x + threadIdx.x;
    if (i < N) { g_cnts[i] = 0; g_cntd[i] = 0; }
    if (i == 0) {
        if (extra == 1) out[base] = (float)comm;
        else if (extra >= 2) *(long long*)(out + base) = comm;
    }
}

// ---------------- launch ----------------
extern "C" void kernel_launch(void* const* d_in, const int* in_sizes, int n_in,
                              void* d_out, int out_size) {
    const float* A = (const float*)d_in[0];
    const float* b = (const float*)d_in[1];
    const float* x = (const float*)d_in[2];
    const int* ei = (const int*)d_in[3];
    int N = in_sizes[1] / D;
    int E = in_sizes[3] / 2;
    const int* src = ei;
    const int* dst = ei + E;
    float* out = (float*)d_out;

    const int TB = 256;
    int nb = (N + SCB - 1) / SCB;
    int total8 = N * (D * D / 8);

    k_convert<<<(total8 + TB - 1) / TB, TB>>>(A, total8);       // 0
    k_count<<<(E + TB - 1) / TB, TB>>>(src, dst, E);            // 1
    k_prep_deg<<<nb, SCB>>>(N);                                  // 2
    k_grad_init<<<(N + 1) / 2, 128>>>(b, x, N);                  // 3 (profiled)
    k_scan_partials<<<1, 128>>>(nb, N, E);                       // 4
    k_rowfill<<<nb, SCB>>>(N);                                   // 5
    k_fill<<<(E + TB - 1) / TB, TB>>>(src, dst, E);              // 6

    int blocks = (N + 1) / 2;
    for (int l = 0; l < NLAYERS; l++) {
        int ib = l & 1;
        int ob = (l + 1) & 1;
        k_layer<<<blocks, 128>>>(b, out, ib, ob, (l == NLAYERS - 1) ? 1 : 0, N);
    }

    int extra = out_size - N * D;
    k_cleanup<<<(N + TB - 1) / TB, TB>>>(out, N * D, extra < 0 ? 0 : extra,
                                         (long long)(3 * NLAYERS) * E, N);
}

// round 7
// speedup vs baseline: 1.6273x; 1.6273x over previous
#include <cuda_runtime.h>
#include <cuda_fp16.h>

#define D 64
#define MAXN 20000
#define MAXE 320000
#define STEP 0.01f
#define NLAYERS 10
#define SCB 256
#define PADH 72   // padded row stride in halves (144 B) -> conflict-free LDS.128

// ---------------- device scratch ----------------
__device__ __half g_Ah[(size_t)MAXN * D * D];   // fp16 copy of A (164 MB)
__device__ float g_tsys[2][MAXN * 128];         // per-node [ts(64)|ys(64)], double buffered
__device__ float g_vs[2][MAXN];
__device__ float g_gprev[MAXN * D];
__device__ float g_invdeg[MAXN];
__device__ int   g_cnts[MAXN];                  // zero at load; re-zeroed by cleanup
__device__ int   g_cntd[MAXN];
__device__ int   g_partial[128];
__device__ int   g_rowstart[MAXN + 1];
__device__ int   g_cursor[MAXN];
__device__ int   g_srcidx[MAXE];

// ---------------- cp.async with L2 evict_first (A stream must not thrash L2) ----------------
__device__ __forceinline__ unsigned long long mk_policy_ef() {
    unsigned long long p;
    asm volatile("createpolicy.fractional.L2::evict_first.b64 %0, 1.0;\n" : "=l"(p));
    return p;
}
__device__ __forceinline__ void cp_async16_ef(void* smem, const void* gmem,
                                              unsigned long long policy) {
    unsigned s = (unsigned)__cvta_generic_to_shared(smem);
    asm volatile("cp.async.cg.shared.global.L2::cache_hint [%0], [%1], 16, %2;\n"
                 :: "r"(s), "l"(gmem), "l"(policy));
}
__device__ __forceinline__ void cp_commit() { asm volatile("cp.async.commit_group;\n"); }
__device__ __forceinline__ void cp_wait0()  { asm volatile("cp.async.wait_group 0;\n"); }

// ---------------- setup ----------------
__global__ void k_count(const int* __restrict__ src,
                        const int* __restrict__ dst, int E) {
    int e = blockIdx.x * blockDim.x + threadIdx.x;
    if (e < E) {
        atomicAdd(&g_cnts[src[e]], 1);
        atomicAdd(&g_cntd[dst[e]], 1);
    }
}

__global__ void k_prep_deg(int N) {
    __shared__ int s[SCB];
    int i = blockIdx.x * SCB + threadIdx.x;
    int c = 0;
    if (i < N) {
        g_invdeg[i] = 1.0f / (1.0f + (float)g_cnts[i]);
        c = g_cntd[i];
    }
    s[threadIdx.x] = c;
    __syncthreads();
    for (int o = SCB / 2; o > 0; o >>= 1) {
        if (threadIdx.x < o) s[threadIdx.x] += s[threadIdx.x + o];
        __syncthreads();
    }
    if (threadIdx.x == 0) g_partial[blockIdx.x] = s[0];
}

__global__ void k_scan_partials(int nb, int N, int E) {
    __shared__ int s[128];
    int t = threadIdx.x;
    int v = (t < nb) ? g_partial[t] : 0;
    s[t] = v;
    __syncthreads();
    for (int o = 1; o < 128; o <<= 1) {
        int a = (t >= o) ? s[t - o] : 0;
        __syncthreads();
        s[t] += a;
        __syncthreads();
    }
    if (t < nb) g_partial[t] = s[t] - v;   // exclusive
    if (t == 0) g_rowstart[N] = E;
}

__global__ void k_rowfill(int N) {
    __shared__ int s[SCB];
    int i = blockIdx.x * SCB + threadIdx.x;
    int c = (i < N) ? g_cntd[i] : 0;
    s[threadIdx.x] = c;
    __syncthreads();
    for (int o = 1; o < SCB; o <<= 1) {
        int a = (threadIdx.x >= o) ? s[threadIdx.x - o] : 0;
        __syncthreads();
        s[threadIdx.x] += a;
        __syncthreads();
    }
    if (i < N) {
        int excl = s[threadIdx.x] - c + g_partial[blockIdx.x];
        g_rowstart[i] = excl;
        g_cursor[i]   = excl;
    }
}

__global__ void k_fill(const int* __restrict__ src,
                       const int* __restrict__ dst, int E) {
    int e = blockIdx.x * blockDim.x + threadIdx.x;
    if (e < E) {
        int pos = atomicAdd(&g_cursor[dst[e]], 1);
        g_srcidx[pos] = src[e];
    }
}

// GEMV row dot from fp16 smem tile, fp32 x in smem, fp32 accumulate
__device__ __forceinline__ float gemv_row(const __half* row, const float* xv) {
    float acc = 0.0f;
#pragma unroll
    for (int j = 0; j < 8; j++) {
        uint4 pk = *(const uint4*)(row + 8 * j);
        const __half2* hp = (const __half2*)&pk;
        float4 x0 = *(const float4*)(xv + 8 * j);
        float4 x1 = *(const float4*)(xv + 8 * j + 4);
        float2 f0 = __half22float2(hp[0]);
        float2 f1 = __half22float2(hp[1]);
        float2 f2 = __half22float2(hp[2]);
        float2 f3 = __half22float2(hp[3]);
        acc += f0.x * x0.x + f0.y * x0.y + f1.x * x0.z + f1.y * x0.w;
        acc += f2.x * x1.x + f2.y * x1.y + f3.x * x1.z + f3.y * x1.w;
    }
    return acc;
}

// ---------------- grad_init + A convert (fused): 2 nodes / 128 threads ----------------
// reads fp32 A linearly (coalesced, streaming), converts to fp16 once:
//   -> g_Ah (for the 10 layer passes)   -> smem tile (for this kernel's GEMV)
// then g0 = 2*Ã x + b (consistent with layers' Ã), seeds ts/ys/vs.
__global__ void __launch_bounds__(128) k_grad_init(
        const float* __restrict__ A, const float* __restrict__ b,
        const float* __restrict__ x, int N) {
    __shared__ __align__(16) __half tile[2][D * PADH];
    __shared__ __align__(16) float xs[2][D];
    int tid = threadIdx.x;
    int local = tid >> 6;
    int t = tid & 63;
    int n = blockIdx.x * 2 + local;
    bool ok = (n < N);
    int nc = ok ? n : (N - 1);

#pragma unroll
    for (int nd = 0; nd < 2; nd++) {
        int nn = min(blockIdx.x * 2 + nd, N - 1);
        const float4* src = (const float4*)(A + (size_t)nn * (D * D));
        __half* dsth = g_Ah + (size_t)nn * (D * D);
#pragma unroll
        for (int k = 0; k < 4; k++) {
            int q = k * 128 + tid;            // 8-half chunk id, 0..511
            float4 f0 = __ldcs(src + 2 * q);
            float4 f1 = __ldcs(src + 2 * q + 1);
            __half2 h[4];
            h[0] = __floats2half2_rn(f0.x, f0.y);
            h[1] = __floats2half2_rn(f0.z, f0.w);
            h[2] = __floats2half2_rn(f1.x, f1.y);
            h[3] = __floats2half2_rn(f1.z, f1.w);
            uint4 pk = *(const uint4*)h;
            *(uint4*)(dsth + 8 * q) = pk;                 // coalesced STG.128
            int r = q >> 3, c = (q & 7) * 8;
            *(uint4*)&tile[nd][r * PADH + c] = pk;        // STS.128 (padded)
        }
    }
    xs[local][t] = x[nc * D + t];
    __syncthreads();

    float acc = gemv_row(&tile[local][t * PADH], xs[local]);
    if (!ok) return;
    float g = 2.0f * acc + b[n * D + t];
    float id = g_invdeg[n];
    g_gprev[n * D + t] = g;
    g_tsys[0][n * 128 + t]      = (xs[local][t] - STEP * g) * id;
    g_tsys[0][n * 128 + 64 + t] = g * id;
    if (t == 0) g_vs[0][n] = id;
}

// ---------------- fused per-layer kernel: 2 nodes / 128 threads ----------------
__global__ void __launch_bounds__(128) k_layer(
        const float* __restrict__ b, float* __restrict__ out,
        int ib, int ob, int last, int N) {
    __shared__ __align__(16) __half tile[2][D * PADH];
    __shared__ __align__(16) float sh[2][128];
    __shared__ float shv[2];
    int tid = threadIdx.x;
    int local = tid >> 6;
    int t = tid & 63;
    int lane = t & 31;
    int n = blockIdx.x * 2 + local;
    bool ok = (n < N);
    int nc = ok ? n : (N - 1);

    // 1) kick off fp16 A staging with evict_first (don't thrash the gather set in L2)
    {
        unsigned long long pol = mk_policy_ef();
#pragma unroll
        for (int nd = 0; nd < 2; nd++) {
            int nn = min(blockIdx.x * 2 + nd, N - 1);
            const __half* src = g_Ah + (size_t)nn * (D * D);
#pragma unroll
            for (int k = 0; k < 4; k++) {
                int q = k * 128 + tid;        // 8-half chunk, 0..511
                int r = q >> 3;
                int c = (q & 7) * 8;
                cp_async16_ef(&tile[nd][r * PADH + c], src + q * 8, pol);
            }
        }
        cp_commit();
    }

    // 2) gather (mix): shfl-broadcast indices (1 coalesced index load / 32 edges / warp),
    //    4-wide unrolled with independent accumulators.
    //    float2 slot t covers floats (2t,2t+1) of the node's [ts|ys] record.
    const float2* tin = (const float2*)g_tsys[ib];
    const float* vin = g_vs[ib];
    int rs = g_rowstart[nc];
    int re = g_rowstart[nc + 1];
    float2 a0 = tin[nc * 64 + t];       // self term (pre-scaled)
    float2 a1 = {0.f, 0.f}, a2 = {0.f, 0.f}, a3 = {0.f, 0.f};
    float vacc = (t == 0) ? vin[nc] : 0.0f;

    for (int base = rs; base < re; base += 32) {
        int kk = base + lane;
        int myidx = (kk < re) ? g_srcidx[kk] : 0;
        int m = min(32, re - base);
        int j = 0;
        for (; j + 4 <= m; j += 4) {
            int s0 = __shfl_sync(0xffffffffu, myidx, j);
            int s1 = __shfl_sync(0xffffffffu, myidx, j + 1);
            int s2 = __shfl_sync(0xffffffffu, myidx, j + 2);
            int s3 = __shfl_sync(0xffffffffu, myidx, j + 3);
            float2 v0 = tin[s0 * 64 + t];
            float2 v1 = tin[s1 * 64 + t];
            float2 v2 = tin[s2 * 64 + t];
            float2 v3 = tin[s3 * 64 + t];
            a0.x += v0.x; a0.y += v0.y;
            a1.x += v1.x; a1.y += v1.y;
            a2.x += v2.x; a2.y += v2.y;
            a3.x += v3.x; a3.y += v3.y;
            if (t == 0) vacc += vin[s0] + vin[s1] + vin[s2] + vin[s3];
        }
        for (; j < m; j++) {
            int s = __shfl_sync(0xffffffffu, myidx, j);
            float2 v = tin[s * 64 + t];
            a0.x += v.x; a0.y += v.y;
            if (t == 0) vacc += vin[s];
        }
    }
    float2 acc;
    acc.x = (a0.x + a1.x) + (a2.x + a3.x);
    acc.y = (a0.y + a1.y) + (a2.y + a3.y);

    // reconstruct mixed record: sh[0..63]=u_new, sh[64..127]=ny
    sh[local][2 * t]     = acc.x;
    sh[local][2 * t + 1] = acc.y;
    if (t == 0) shv[local] = vacc;
    __syncthreads();

    float u_r  = sh[local][t];
    float ny_r = sh[local][64 + t];
    float vnew = shv[local];
    float x1 = u_r / vnew;
    sh[local][t] = x1;            // own-slot overwrite (x vector for GEMV)
    cp_wait0();
    __syncthreads();

    // 3) GEMV from fp16 smem tile
    float accg = gemv_row(&tile[local][t * PADH], sh[local]);
    if (!ok) return;

    float g1 = 2.0f * accg + b[n * D + t];
    float ynew = ny_r + g1 - g_gprev[n * D + t];
    g_gprev[n * D + t] = g1;

    if (last) {
        out[n * D + t] = x1;
    } else {
        float id = g_invdeg[n];
        g_tsys[ob][n * 128 + t]      = (u_r - STEP * ynew) * id;
        g_tsys[ob][n * 128 + 64 + t] = ynew * id;
        if (t == 0) g_vs[ob][n] = vnew * id;
    }
}

// cleanup: re-zero counters for next graph replay + emit comm_cost tail
__global__ void k_cleanup(float* out, int base, int extra, long long comm, int N) {
    int i = blockIdx.x * blockDim.x + threadIdx.x;
    if (i < N) { g_cnts[i] = 0; g_cntd[i] = 0; }
    if (i == 0) {
        if (extra == 1) out[base] = (float)comm;
        else if (extra >= 2) *(long long*)(out + base) = comm;
    }
}

// ---------------- launch ----------------
extern "C" void kernel_launch(void* const* d_in, const int* in_sizes, int n_in,
                              void* d_out, int out_size) {
    const float* A = (const float*)d_in[0];
    const float* b = (const float*)d_in[1];
    const float* x = (const float*)d_in[2];
    const int* ei = (const int*)d_in[3];
    int N = in_sizes[1] / D;
    int E = in_sizes[3] / 2;
    const int* src = ei;
    const int* dst = ei + E;
    float* out = (float*)d_out;

    const int TB = 256;
    int nb = (N + SCB - 1) / SCB;

    k_count<<<(E + TB - 1) / TB, TB>>>(src, dst, E);            // 0
    k_prep_deg<<<nb, SCB>>>(N);                                  // 1
    k_scan_partials<<<1, 128>>>(nb, N, E);                       // 2
    k_grad_init<<<(N + 1) / 2, 128>>>(A, b, x, N);               // 3 (profiled)
    k_rowfill<<<nb, SCB>>>(N);                                   // 4
    k_fill<<<(E + TB - 1) / TB, TB>>>(src, dst, E);              // 5

    int blocks = (N + 1) / 2;
    for (int l = 0; l < NLAYERS; l++) {
        int ib = l & 1;
        int ob = (l + 1) & 1;
        k_layer<<<blocks, 128>>>(b, out, ib, ob, (l == NLAYERS - 1) ? 1 : 0, N);
    }

    int extra = out_size - N * D;
    k_cleanup<<<(N + TB - 1) / TB, TB>>>(out, N * D, extra < 0 ? 0 : extra,
                                         (long long)(3 * NLAYERS) * E, N);
}